// round 2
// baseline (speedup 1.0000x reference)
#include <cuda_runtime.h>
#include <cstddef>

#define BATCH 32
#define NOBJ  64
#define FDIM  128
#define D2    256
#define ROWS1 (BATCH*NOBJ)          // 2048
#define PAIRROWS (BATCH*NOBJ*NOBJ)  // 131072
#define P0_SIZE (ROWS1*FDIM)        // 262144
#define PAIR_SIZE ((size_t)PAIRROWS*D2) // 33554432

// Scratch: A[pred][row][c] = x_row @ W1_top + b1 ; C[pred][row][c] = x_row @ W1_bot
__device__ float g_A[3*ROWS1*D2];
__device__ float g_C[3*ROWS1*D2];

__device__ __forceinline__ float mish_f(float x) {
    // softplus via stable logaddexp(x,0); matches jax.nn.softplus
    float sp = fmaxf(x, 0.0f) + log1pf(__expf(-fabsf(x)));
    return x * tanhf(sp);
}

// ---------------------------------------------------------------------------
// Precompute A and C for predicates p1..p3.
// grid (128, 3), block 256. Each CTA: 16 rows x 256 cols, K=128, for A and C.
// ---------------------------------------------------------------------------
__global__ __launch_bounds__(256) void precompute_AC(
    const float* __restrict__ emb,
    const float* __restrict__ W1a, const float* __restrict__ b1a,
    const float* __restrict__ W1b, const float* __restrict__ b1b,
    const float* __restrict__ W1c, const float* __restrict__ b1c)
{
    int pred = blockIdx.y;
    const float* W1 = (pred == 0) ? W1a : (pred == 1) ? W1b : W1c;
    const float* b1 = (pred == 0) ? b1a : (pred == 1) ? b1b : b1c;
    int row0 = blockIdx.x * 16;

    __shared__ float Xs[16][FDIM];
    int tid = threadIdx.x;
    #pragma unroll
    for (int q = 0; q < 8; q++) {
        int e = tid + 256 * q;                  // 2048 elements
        Xs[e >> 7][e & 127] = emb[(size_t)row0 * FDIM + e];
    }
    __syncthreads();

    int c = tid;                                 // 0..255
    float accA[16], accC[16];
    float bb = b1[c];
    #pragma unroll
    for (int r = 0; r < 16; r++) { accA[r] = bb; accC[r] = 0.0f; }

    for (int k = 0; k < FDIM; k++) {
        float wA = W1[(size_t)k * D2 + c];          // top half rows
        float wC = W1[(size_t)(FDIM + k) * D2 + c]; // bottom half rows
        #pragma unroll
        for (int r = 0; r < 16; r++) {
            float x = Xs[r][k];                  // broadcast
            accA[r] = fmaf(x, wA, accA[r]);
            accC[r] = fmaf(x, wC, accC[r]);
        }
    }

    float* Ap = g_A + ((size_t)pred * ROWS1 + row0) * D2 + c;
    float* Cp = g_C + ((size_t)pred * ROWS1 + row0) * D2 + c;
    #pragma unroll
    for (int r = 0; r < 16; r++) {
        Ap[(size_t)r * D2] = accA[r];
        Cp[(size_t)r * D2] = accC[r];
    }
}

// ---------------------------------------------------------------------------
// p0: full fused residual MLP on 2048x128 rows. grid 128, block 128.
// ---------------------------------------------------------------------------
__global__ __launch_bounds__(128) void p0_kernel(
    const float* __restrict__ emb,
    const float* __restrict__ W1, const float* __restrict__ b1,
    const float* __restrict__ W2, const float* __restrict__ b2,
    float* __restrict__ out)
{
    int row0 = blockIdx.x * 16;
    __shared__ float Xs[16][FDIM];
    __shared__ float Hs[16][FDIM];
    int tid = threadIdx.x;                       // 0..127
    #pragma unroll
    for (int q = 0; q < 16; q++) {
        int e = tid + 128 * q;                   // 2048 elements
        Xs[e >> 7][e & 127] = emb[(size_t)row0 * FDIM + e];
    }
    __syncthreads();

    int c = tid;
    float acc[16];
    float bb = b1[c];
    #pragma unroll
    for (int r = 0; r < 16; r++) acc[r] = bb;
    for (int k = 0; k < FDIM; k++) {
        float w = W1[(size_t)k * FDIM + c];
        #pragma unroll
        for (int r = 0; r < 16; r++) acc[r] = fmaf(Xs[r][k], w, acc[r]);
    }
    #pragma unroll
    for (int r = 0; r < 16; r++) Hs[r][c] = mish_f(acc[r]);
    __syncthreads();

    float bb2 = b2[c];
    #pragma unroll
    for (int r = 0; r < 16; r++) acc[r] = bb2;
    for (int k = 0; k < FDIM; k++) {
        float w = W2[(size_t)k * FDIM + c];
        #pragma unroll
        for (int r = 0; r < 16; r++) acc[r] = fmaf(Hs[r][k], w, acc[r]);
    }
    #pragma unroll
    for (int r = 0; r < 16; r++)
        out[(size_t)(row0 + r) * FDIM + c] = Xs[r][c] + acc[r];
}

// ---------------------------------------------------------------------------
// Pair kernel: one CTA per (pred, b, i). Computes the 64(j) x 256 output tile:
//   out[j, :] = [x_i ‖ x_j] + mish(A[i] + C[j]) @ W2 + b2
// K=256 in chunks of 32; W2 panel + transposed H in smem; 8x8 register tile.
// ---------------------------------------------------------------------------
__global__ __launch_bounds__(256, 2) void pair_kernel(
    const float* __restrict__ emb,
    const float* __restrict__ W2a, const float* __restrict__ b2a,
    const float* __restrict__ W2b, const float* __restrict__ b2b,
    const float* __restrict__ W2c, const float* __restrict__ b2c,
    float* __restrict__ out1)
{
    int i = blockIdx.x, b = blockIdx.y, pred = blockIdx.z;
    const float* W2 = (pred == 0) ? W2a : (pred == 1) ? W2b : W2c;
    const float* b2 = (pred == 0) ? b2a : (pred == 1) ? b2b : b2c;
    const float* Arow  = g_A + ((size_t)pred * ROWS1 + b * NOBJ + i) * D2;
    const float* Cbase = g_C + ((size_t)pred * ROWS1 + b * NOBJ) * D2;
    float* outp = out1 + (size_t)pred * PAIR_SIZE
                       + (size_t)((b * NOBJ + i) * NOBJ) * D2;

    __shared__ float Ws[32][D2];      // 32 KB: W2 k-panel
    __shared__ float HsT[32][65];     // 8.1 KB: transposed mish activations, pad=65

    int tid = threadIdx.x;
    int ty = tid >> 5;                // 0..7  -> j block
    int tx = tid & 31;                // 0..31 -> col block

    float acc[8][8];
    #pragma unroll
    for (int r = 0; r < 8; r++)
        #pragma unroll
        for (int c = 0; c < 8; c++) acc[r][c] = 0.0f;

    for (int kc = 0; kc < D2; kc += 32) {
        __syncthreads();
        // Stage W2 panel (rows kc..kc+31, all 256 cols) — coalesced float4
        const float4* src = (const float4*)(W2 + (size_t)kc * D2);
        float4* dst = (float4*)(&Ws[0][0]);
        #pragma unroll
        for (int q = 0; q < 8; q++) dst[tid + 256 * q] = src[tid + 256 * q];

        // Compute transposed H chunk: HsT[k][j] = mish(A[i][kc+k] + C[j][kc+k])
        #pragma unroll
        for (int q = 0; q < 8; q++) {
            int e = tid + 256 * q;    // 2048 = 32k x 64j
            int k = e & 31;           // lane -> coalesced C/A reads
            int j = e >> 5;
            float pre = Arow[kc + k] + Cbase[(size_t)j * D2 + kc + k];
            HsT[k][j] = mish_f(pre);  // (65k+j)%32 distinct over k: no conflicts
        }
        __syncthreads();

        #pragma unroll 4
        for (int k = 0; k < 32; k++) {
            float hh[8], ww[8];
            #pragma unroll
            for (int r = 0; r < 8; r++) hh[r] = HsT[k][ty * 8 + r]; // broadcast
            float4 w0 = *(const float4*)&Ws[k][tx * 8];
            float4 w1 = *(const float4*)&Ws[k][tx * 8 + 4];
            ww[0] = w0.x; ww[1] = w0.y; ww[2] = w0.z; ww[3] = w0.w;
            ww[4] = w1.x; ww[5] = w1.y; ww[6] = w1.z; ww[7] = w1.w;
            #pragma unroll
            for (int r = 0; r < 8; r++)
                #pragma unroll
                for (int c = 0; c < 8; c++)
                    acc[r][c] = fmaf(hh[r], ww[c], acc[r][c]);
        }
    }

    // Epilogue: residual [x_i ‖ x_j] + bias
    const float* embI = emb + (size_t)(b * NOBJ + i) * FDIM;
    float bias[8], resI[8];
    #pragma unroll
    for (int c = 0; c < 8; c++) {
        int col = tx * 8 + c;
        bias[c] = b2[col];
        resI[c] = (col < FDIM) ? embI[col] : 0.0f;
    }
    bool leftHalf = (tx < 16);        // cols tx*8..tx*8+7 entirely in one half
    #pragma unroll
    for (int r = 0; r < 8; r++) {
        int j = ty * 8 + r;
        const float* embJ = emb + (size_t)(b * NOBJ + j) * FDIM;
        float* orow = outp + (size_t)j * D2;
        float v[8];
        #pragma unroll
        for (int c = 0; c < 8; c++) {
            int col = tx * 8 + c;
            float res = leftHalf ? resI[c] : embJ[col - FDIM];
            v[c] = acc[r][c] + res + bias[c];
        }
        *(float4*)&orow[tx * 8]     = make_float4(v[0], v[1], v[2], v[3]);
        *(float4*)&orow[tx * 8 + 4] = make_float4(v[4], v[5], v[6], v[7]);
    }
}

// ---------------------------------------------------------------------------
extern "C" void kernel_launch(void* const* d_in, const int* in_sizes, int n_in,
                              void* d_out, int out_size)
{
    const float* emb   = (const float*)d_in[0];
    // d_in[1] = num_objects (uniform = NOBJ, unused)
    const float* W1_p0 = (const float*)d_in[2];
    const float* b1_p0 = (const float*)d_in[3];
    const float* W2_p0 = (const float*)d_in[4];
    const float* b2_p0 = (const float*)d_in[5];
    const float* W1_p1 = (const float*)d_in[6];
    const float* b1_p1 = (const float*)d_in[7];
    const float* W2_p1 = (const float*)d_in[8];
    const float* b2_p1 = (const float*)d_in[9];
    const float* W1_p2 = (const float*)d_in[10];
    const float* b1_p2 = (const float*)d_in[11];
    const float* W2_p2 = (const float*)d_in[12];
    const float* b2_p2 = (const float*)d_in[13];
    const float* W1_p3 = (const float*)d_in[14];
    const float* b1_p3 = (const float*)d_in[15];
    const float* W2_p3 = (const float*)d_in[16];
    const float* b2_p3 = (const float*)d_in[17];

    float* out = (float*)d_out;

    precompute_AC<<<dim3(ROWS1 / 16, 3), 256>>>(
        emb, W1_p1, b1_p1, W1_p2, b1_p2, W1_p3, b1_p3);

    p0_kernel<<<ROWS1 / 16, 128>>>(emb, W1_p0, b1_p0, W2_p0, b2_p0, out);

    pair_kernel<<<dim3(NOBJ, BATCH, 3), 256>>>(
        emb, W2_p1, b2_p1, W2_p2, b2_p2, W2_p3, b2_p3, out + P0_SIZE);
}

// round 6
// speedup vs baseline: 2.0626x; 2.0626x over previous
#include <cuda_runtime.h>
#include <cuda_bf16.h>
#include <cstdint>
#include <cstddef>

#define BATCH 32
#define NOBJ  64
#define FDIM  128
#define D2    256
#define ROWS1 (BATCH*NOBJ)          // 2048
#define P0_SIZE (ROWS1*FDIM)        // 262144
#define PAIR_SIZE ((size_t)BATCH*NOBJ*NOBJ*D2) // 33554432

// ---------------- global scratch (no allocs allowed) ----------------
__device__ __align__(16) float g_A[3*ROWS1*D2];   // A[pred][row][c] = x@W1_top + b1
__device__ __align__(16) float g_C[3*ROWS1*D2];   // C[pred][row][c] = x@W1_bot
__device__ __align__(16) __nv_bfloat16 g_WT_hi[3*D2*D2]; // W2^T[pred][n][k] hi split
__device__ __align__(16) __nv_bfloat16 g_WT_lo[3*D2*D2]; // lo split

// ---------------- fast mish: x * tanh(softplus(x)) ------------------
// tanh(ln(1+e^x)) = (u^2+2u)/(u^2+2u+2), u=e^x.
__device__ __forceinline__ float mish_fast(float x) {
    float u = __expf(fminf(x, 40.0f));
    float n = fmaf(u, u, 2.0f * u);
    return x * __fdividef(n, n + 2.0f);
}

// ---------------- PTX helpers (plain PTX, sm_80+) -------------------
__device__ __forceinline__ uint32_t smem_u32(const void* p) {
    uint32_t a;
    asm("{ .reg .u64 t; cvta.to.shared.u64 t, %1; cvt.u32.u64 %0, t; }"
        : "=r"(a) : "l"(p));
    return a;
}
__device__ __forceinline__ void cp16(uint32_t dst, const void* src) {
    asm volatile("cp.async.cg.shared.global [%0], [%1], 16;" :: "r"(dst), "l"(src));
}
#define CP_COMMIT() asm volatile("cp.async.commit_group;" ::: "memory")
#define CP_WAIT0()  asm volatile("cp.async.wait_group 0;" ::: "memory")

__device__ __forceinline__ void ldsm4(uint32_t (&r)[4], uint32_t addr) {
    asm volatile("ldmatrix.sync.aligned.m8n8.x4.shared.b16 {%0,%1,%2,%3}, [%4];"
                 : "=r"(r[0]), "=r"(r[1]), "=r"(r[2]), "=r"(r[3]) : "r"(addr));
}
__device__ __forceinline__ void mma16816(float* d, const uint32_t* a, const uint32_t* b) {
    asm volatile("mma.sync.aligned.m16n8k16.row.col.f32.bf16.bf16.f32 "
        "{%0,%1,%2,%3}, {%4,%5,%6,%7}, {%8,%9}, {%0,%1,%2,%3};"
        : "+f"(d[0]), "+f"(d[1]), "+f"(d[2]), "+f"(d[3])
        : "r"(a[0]), "r"(a[1]), "r"(a[2]), "r"(a[3]), "r"(b[0]), "r"(b[1]));
}

// smem layout (bytes from dynamic base). Row stride 80B (32 bf16 + 8 pad):
// ldmatrix rows hit banks {20r mod 32}, r=0..7 distinct -> conflict-free.
#define KCH      32
#define ROWB     80
#define W_STAGE  (D2 * ROWB)        // 20480
#define H_STAGE  (128 * ROWB)       // 10240
#define OFF_WHI  0u
#define OFF_WLO  (2u * W_STAGE)     // 40960
#define OFF_HHI  (4u * W_STAGE)     // 81920
#define OFF_HLO  (OFF_HHI + 2u * H_STAGE) // 102400
#define SMEM_PAIR (OFF_HLO + 2u * H_STAGE) // 122880

// ---------------------------------------------------------------------------
// W2 transpose + bf16 split: g_WT[pred][n][k] = split(W2[k][n])
// ---------------------------------------------------------------------------
__global__ __launch_bounds__(256) void split_W2T(
    const float* __restrict__ W2a, const float* __restrict__ W2b,
    const float* __restrict__ W2c)
{
    int pred = blockIdx.z;
    const float* W2 = (pred == 0) ? W2a : (pred == 1) ? W2b : W2c;
    int n0 = blockIdx.x * 32, k0 = blockIdx.y * 32;
    __shared__ float t[32][33];
    int tid = threadIdx.x;
    int c = tid & 31, r8 = tid >> 5;
    #pragma unroll
    for (int q = 0; q < 4; q++) {
        int k = r8 + q * 8;
        t[k][c] = W2[(size_t)(k0 + k) * D2 + n0 + c];
    }
    __syncthreads();
    #pragma unroll
    for (int q = 0; q < 4; q++) {
        int n = r8 + q * 8;
        float v = t[c][n];
        __nv_bfloat16 hi = __float2bfloat16(v);
        __nv_bfloat16 lo = __float2bfloat16(v - __bfloat162float(hi));
        size_t idx = (size_t)pred * D2 * D2 + (size_t)(n0 + n) * D2 + (k0 + c);
        g_WT_hi[idx] = hi;
        g_WT_lo[idx] = lo;
    }
}

// ---------------------------------------------------------------------------
// Precompute A and C for p1..p3 (GEMM1 factorization). grid (128,3), block 256.
// ---------------------------------------------------------------------------
__global__ __launch_bounds__(256) void precompute_AC(
    const float* __restrict__ emb,
    const float* __restrict__ W1a, const float* __restrict__ b1a,
    const float* __restrict__ W1b, const float* __restrict__ b1b,
    const float* __restrict__ W1c, const float* __restrict__ b1c)
{
    int pred = blockIdx.y;
    const float* W1 = (pred == 0) ? W1a : (pred == 1) ? W1b : W1c;
    const float* b1 = (pred == 0) ? b1a : (pred == 1) ? b1b : b1c;
    int row0 = blockIdx.x * 16;

    __shared__ float Xs[16][FDIM];
    int tid = threadIdx.x;
    #pragma unroll
    for (int q = 0; q < 8; q++) {
        int e = tid + 256 * q;
        Xs[e >> 7][e & 127] = emb[(size_t)row0 * FDIM + e];
    }
    __syncthreads();

    int c = tid;
    float accA[16], accC[16];
    float bb = b1[c];
    #pragma unroll
    for (int r = 0; r < 16; r++) { accA[r] = bb; accC[r] = 0.0f; }

    for (int k = 0; k < FDIM; k++) {
        float wA = W1[(size_t)k * D2 + c];
        float wC = W1[(size_t)(FDIM + k) * D2 + c];
        #pragma unroll
        for (int r = 0; r < 16; r++) {
            float x = Xs[r][k];
            accA[r] = fmaf(x, wA, accA[r]);
            accC[r] = fmaf(x, wC, accC[r]);
        }
    }
    float* Ap = g_A + ((size_t)pred * ROWS1 + row0) * D2 + c;
    float* Cp = g_C + ((size_t)pred * ROWS1 + row0) * D2 + c;
    #pragma unroll
    for (int r = 0; r < 16; r++) {
        Ap[(size_t)r * D2] = accA[r];
        Cp[(size_t)r * D2] = accC[r];
    }
}

// ---------------------------------------------------------------------------
// p0: fused residual MLP on 2048x128 rows. grid 128, blk 128.
// ---------------------------------------------------------------------------
__global__ __launch_bounds__(128) void p0_kernel(
    const float* __restrict__ emb,
    const float* __restrict__ W1, const float* __restrict__ b1,
    const float* __restrict__ W2, const float* __restrict__ b2,
    float* __restrict__ out)
{
    int row0 = blockIdx.x * 16;
    __shared__ float Xs[16][FDIM];
    __shared__ float Hs[16][FDIM];
    int tid = threadIdx.x;
    #pragma unroll
    for (int q = 0; q < 16; q++) {
        int e = tid + 128 * q;
        Xs[e >> 7][e & 127] = emb[(size_t)row0 * FDIM + e];
    }
    __syncthreads();

    int c = tid;
    float acc[16];
    float bb = b1[c];
    #pragma unroll
    for (int r = 0; r < 16; r++) acc[r] = bb;
    for (int k = 0; k < FDIM; k++) {
        float w = W1[(size_t)k * FDIM + c];
        #pragma unroll
        for (int r = 0; r < 16; r++) acc[r] = fmaf(Xs[r][k], w, acc[r]);
    }
    #pragma unroll
    for (int r = 0; r < 16; r++) Hs[r][c] = mish_fast(acc[r]);
    __syncthreads();

    float bb2 = b2[c];
    #pragma unroll
    for (int r = 0; r < 16; r++) acc[r] = bb2;
    for (int k = 0; k < FDIM; k++) {
        float w = W2[(size_t)k * FDIM + c];
        #pragma unroll
        for (int r = 0; r < 16; r++) acc[r] = fmaf(Hs[r][k], w, acc[r]);
    }
    #pragma unroll
    for (int r = 0; r < 16; r++)
        out[(size_t)(row0 + r) * FDIM + c] = Xs[r][c] + acc[r];
}

// ---------------------------------------------------------------------------
// Pair kernel via mma.sync bf16 (3-term split). One CTA per (pred, b, i-pair).
//   M=128 (2 i x 64 j), N=256, K=256 in 8 chunks of 32. 512 thr / 16 warps.
//   Warp tile m32 x n64. W via cp.async double-buffer; H mish computed here.
// ---------------------------------------------------------------------------
__global__ __launch_bounds__(512, 1) void pair_mma_kernel(
    const float* __restrict__ emb,
    const float* __restrict__ b2a, const float* __restrict__ b2b,
    const float* __restrict__ b2c,
    float* __restrict__ out1)
{
    extern __shared__ char sptr[];
    uint32_t sbase = smem_u32(sptr);

    int tid = threadIdx.x;
    int wid = tid >> 5;
    int lane = tid & 31;
    int warpM = wid & 3;       // 4 groups of 32 M-rows
    int warpN = wid >> 2;      // 4 groups of 64 N-cols
    int i0 = blockIdx.x * 2, b = blockIdx.y, pred = blockIdx.z;
    const float* b2 = (pred == 0) ? b2a : (pred == 1) ? b2b : b2c;

    const float* Arow0 = g_A + ((size_t)pred * ROWS1 + b * NOBJ + i0) * D2;
    const float* Cbase = g_C + ((size_t)pred * ROWS1 + b * NOBJ) * D2;
    const __nv_bfloat16* WHi = g_WT_hi + (size_t)pred * D2 * D2;
    const __nv_bfloat16* WLo = g_WT_lo + (size_t)pred * D2 * D2;

    float acc[2][8][4];
    #pragma unroll
    for (int mt = 0; mt < 2; mt++)
        #pragma unroll
        for (int nt = 0; nt < 8; nt++)
            #pragma unroll
            for (int q = 0; q < 4; q++) acc[mt][nt][q] = 0.0f;

    // ---- W chunk loader (cp.async): 256n x 32k, hi+lo -> stage st ----
    auto loadW = [&](int kc, int st) {
        #pragma unroll
        for (int q = 0; q < 4; q++) {
            int idx = tid + 512 * q;          // 0..2047 16B-granules
            int split = idx >> 10;
            int r = idx & 1023;
            int n = r >> 2, gi = r & 3;
            const __nv_bfloat16* src =
                (split ? WLo : WHi) + (size_t)n * D2 + kc + gi * 8;
            uint32_t dst = sbase + (split ? OFF_WLO : OFF_WHI)
                         + (uint32_t)st * W_STAGE + n * ROWB + gi * 16;
            cp16(dst, src);
        }
    };

    // ---- H chunk: 128m x 32k mish + bf16 split -> stage st ----
    auto computeH = [&](int kc, int st) {
        int m = tid >> 2, ko = (tid & 3) * 8;
        const float* aP = Arow0 + (m >> 6) * D2 + kc + ko;
        const float* cP = Cbase + (size_t)(m & 63) * D2 + kc + ko;
        float4 a0 = *(const float4*)aP, a1 = *(const float4*)(aP + 4);
        float4 c0 = *(const float4*)cP, c1 = *(const float4*)(cP + 4);
        float h[8];
        h[0] = mish_fast(a0.x + c0.x); h[1] = mish_fast(a0.y + c0.y);
        h[2] = mish_fast(a0.z + c0.z); h[3] = mish_fast(a0.w + c0.w);
        h[4] = mish_fast(a1.x + c1.x); h[5] = mish_fast(a1.y + c1.y);
        h[6] = mish_fast(a1.z + c1.z); h[7] = mish_fast(a1.w + c1.w);
        uint32_t hw[4], lw[4];
        #pragma unroll
        for (int q = 0; q < 4; q++) {
            __nv_bfloat16 b0 = __float2bfloat16(h[2*q]);
            __nv_bfloat16 b1 = __float2bfloat16(h[2*q+1]);
            __nv_bfloat162 hp; hp.x = b0; hp.y = b1;
            __nv_bfloat162 lp;
            lp.x = __float2bfloat16(h[2*q]   - __bfloat162float(b0));
            lp.y = __float2bfloat16(h[2*q+1] - __bfloat162float(b1));
            hw[q] = *reinterpret_cast<uint32_t*>(&hp);
            lw[q] = *reinterpret_cast<uint32_t*>(&lp);
        }
        uint32_t off = (uint32_t)st * H_STAGE + m * ROWB + ko * 2;
        *(uint4*)(sptr + OFF_HHI + off) = make_uint4(hw[0], hw[1], hw[2], hw[3]);
        *(uint4*)(sptr + OFF_HLO + off) = make_uint4(lw[0], lw[1], lw[2], lw[3]);
    };

    // ---- MMA over one k-chunk (32) in stage st ----
    auto mmaChunk = [&](int st) {
        uint32_t hHi = sbase + OFF_HHI + (uint32_t)st * H_STAGE;
        uint32_t hLo = sbase + OFF_HLO + (uint32_t)st * H_STAGE;
        uint32_t wHi = sbase + OFF_WHI + (uint32_t)st * W_STAGE;
        uint32_t wLo = sbase + OFF_WLO + (uint32_t)st * W_STAGE;
        #pragma unroll
        for (int ks = 0; ks < 2; ks++) {
            int kl = ks * 16;
            uint32_t ahi[2][4], alo[2][4];
            int arow = lane & 15;
            int acol = kl + ((lane >> 4) << 3);
            #pragma unroll
            for (int mt = 0; mt < 2; mt++) {
                uint32_t rowG = warpM * 32 + mt * 16 + arow;
                ldsm4(ahi[mt], hHi + rowG * ROWB + acol * 2);
                ldsm4(alo[mt], hLo + rowG * ROWB + acol * 2);
            }
            int g = lane >> 3;
            int brow = (g >> 1) * 8 + (lane & 7);
            int bcol = kl + ((g & 1) << 3);
            #pragma unroll
            for (int p = 0; p < 4; p++) {
                uint32_t nG = warpN * 64 + p * 16 + brow;
                uint32_t bhi[4], blo[4];
                ldsm4(bhi, wHi + nG * ROWB + bcol * 2);
                ldsm4(blo, wLo + nG * ROWB + bcol * 2);
                #pragma unroll
                for (int mt = 0; mt < 2; mt++) {
                    #pragma unroll
                    for (int hh = 0; hh < 2; hh++) {
                        float* d = acc[mt][p * 2 + hh];
                        mma16816(d, ahi[mt], &bhi[hh * 2]);
                        mma16816(d, ahi[mt], &blo[hh * 2]);
                        mma16816(d, alo[mt], &bhi[hh * 2]);
                    }
                }
            }
        }
    };

    // ---- pipelined main loop ----
    loadW(0, 0); CP_COMMIT();
    computeH(0, 0);
    CP_WAIT0();
    __syncthreads();
    #pragma unroll 1
    for (int c = 0; c < 8; c++) {
        int cur = c & 1, nxt = cur ^ 1;
        if (c < 7) {
            loadW((c + 1) * KCH, nxt); CP_COMMIT();
            computeH((c + 1) * KCH, nxt);
        }
        mmaChunk(cur);
        if (c < 7) CP_WAIT0();
        __syncthreads();
    }

    // ---- epilogue: residual + bias, st.v2 ----
    int rowTile = lane >> 2, colq = (lane & 3) * 2;
    #pragma unroll
    for (int mt = 0; mt < 2; mt++) {
        #pragma unroll
        for (int rh = 0; rh < 2; rh++) {
            int mG = warpM * 32 + mt * 16 + rh * 8 + rowTile;
            int ii = mG >> 6, j = mG & 63;
            const float* resP = (warpN < 2)
                ? emb + (size_t)(b * NOBJ + i0 + ii) * FDIM
                : emb + (size_t)(b * NOBJ + j) * FDIM;
            float* orow = out1 + (size_t)pred * PAIR_SIZE
                        + (size_t)((b * NOBJ + i0 + ii) * NOBJ + j) * D2;
            #pragma unroll
            for (int nt = 0; nt < 8; nt++) {
                int col = warpN * 64 + nt * 8 + colq;
                float2 res  = *(const float2*)(resP + (col & 127));
                float2 bias = *(const float2*)(b2 + col);
                float2 v;
                v.x = acc[mt][nt][rh * 2 + 0] + res.x + bias.x;
                v.y = acc[mt][nt][rh * 2 + 1] + res.y + bias.y;
                *(float2*)(orow + col) = v;
            }
        }
    }
}

// ---------------------------------------------------------------------------
extern "C" void kernel_launch(void* const* d_in, const int* in_sizes, int n_in,
                              void* d_out, int out_size)
{
    const float* emb   = (const float*)d_in[0];
    const float* W1_p0 = (const float*)d_in[2];
    const float* b1_p0 = (const float*)d_in[3];
    const float* W2_p0 = (const float*)d_in[4];
    const float* b2_p0 = (const float*)d_in[5];
    const float* W1_p1 = (const float*)d_in[6];
    const float* b1_p1 = (const float*)d_in[7];
    const float* W2_p1 = (const float*)d_in[8];
    const float* b2_p1 = (const float*)d_in[9];
    const float* W1_p2 = (const float*)d_in[10];
    const float* b1_p2 = (const float*)d_in[11];
    const float* W2_p2 = (const float*)d_in[12];
    const float* b2_p2 = (const float*)d_in[13];
    const float* W1_p3 = (const float*)d_in[14];
    const float* b1_p3 = (const float*)d_in[15];
    const float* W2_p3 = (const float*)d_in[16];
    const float* b2_p3 = (const float*)d_in[17];

    float* out = (float*)d_out;

    cudaFuncSetAttribute(pair_mma_kernel,
                         cudaFuncAttributeMaxDynamicSharedMemorySize, SMEM_PAIR);

    split_W2T<<<dim3(8, 8, 3), 256>>>(W2_p1, W2_p2, W2_p3);

    precompute_AC<<<dim3(ROWS1 / 16, 3), 256>>>(
        emb, W1_p1, b1_p1, W1_p2, b1_p2, W1_p3, b1_p3);

    p0_kernel<<<ROWS1 / 16, 128>>>(emb, W1_p0, b1_p0, W2_p0, b2_p0, out);

    pair_mma_kernel<<<dim3(NOBJ / 2, BATCH, 3), 512, SMEM_PAIR>>>(
        emb, b2_p1, b2_p2, b2_p3, out + P0_SIZE);
}

// round 7
// speedup vs baseline: 2.1648x; 1.0495x over previous
#include <cuda_runtime.h>
#include <cuda_bf16.h>
#include <cstdint>
#include <cstddef>

#define BATCH 32
#define NOBJ  64
#define FDIM  128
#define D2    256
#define ROWS1 (BATCH*NOBJ)          // 2048
#define P0_SIZE (ROWS1*FDIM)        // 262144
#define PAIR_SIZE ((size_t)BATCH*NOBJ*NOBJ*D2) // 33554432

// ---------------- global scratch (no allocs allowed) ----------------
__device__ __align__(16) float g_A[3*ROWS1*D2];   // A[pred][row][c] = x@W1_top + b1
__device__ __align__(16) float g_C[3*ROWS1*D2];   // C[pred][row][c] = x@W1_bot
__device__ __align__(16) __nv_bfloat16 g_WT_hi[3*D2*D2]; // W2^T[pred][n][k] hi split
__device__ __align__(16) __nv_bfloat16 g_WT_lo[3*D2*D2]; // lo split

// ---------------- fast mish: x * tanh(softplus(x)) ------------------
__device__ __forceinline__ float mish_fast(float x) {
    float u = __expf(fminf(x, 40.0f));
    float n = fmaf(u, u, 2.0f * u);
    return x * __fdividef(n, n + 2.0f);
}

// ---------------- PTX helpers -------------------
__device__ __forceinline__ uint32_t smem_u32(const void* p) {
    uint32_t a;
    asm("{ .reg .u64 t; cvta.to.shared.u64 t, %1; cvt.u32.u64 %0, t; }"
        : "=r"(a) : "l"(p));
    return a;
}
__device__ __forceinline__ void cp16(uint32_t dst, const void* src) {
    asm volatile("cp.async.cg.shared.global [%0], [%1], 16;" :: "r"(dst), "l"(src));
}
#define CP_COMMIT() asm volatile("cp.async.commit_group;" ::: "memory")
#define CP_WAIT0()  asm volatile("cp.async.wait_group 0;" ::: "memory")

__device__ __forceinline__ void ldsm4(uint32_t (&r)[4], uint32_t addr) {
    asm volatile("ldmatrix.sync.aligned.m8n8.x4.shared.b16 {%0,%1,%2,%3}, [%4];"
                 : "=r"(r[0]), "=r"(r[1]), "=r"(r[2]), "=r"(r[3]) : "r"(addr));
}
__device__ __forceinline__ void mma16816(float* d, const uint32_t* a, const uint32_t* b) {
    asm volatile("mma.sync.aligned.m16n8k16.row.col.f32.bf16.bf16.f32 "
        "{%0,%1,%2,%3}, {%4,%5,%6,%7}, {%8,%9}, {%0,%1,%2,%3};"
        : "+f"(d[0]), "+f"(d[1]), "+f"(d[2]), "+f"(d[3])
        : "r"(a[0]), "r"(a[1]), "r"(a[2]), "r"(a[3]), "r"(b[0]), "r"(b[1]));
}

// smem layout (bytes from dynamic base). Row stride 80B (32 bf16 + 8 pad):
// ldmatrix rows hit banks {20r mod 32}, r=0..7 distinct -> conflict-free.
#define KCH      32
#define ROWB     80
#define W_STAGE  (128 * ROWB)       // 10240 (N-half: 128 rows)
#define H_STAGE  (128 * ROWB)       // 10240
#define OFF_WHI  0u
#define OFF_WLO  (2u * W_STAGE)     // 20480
#define OFF_HHI  (4u * W_STAGE)     // 40960
#define OFF_HLO  (OFF_HHI + 2u * H_STAGE) // 61440
#define SMEM_PAIR (OFF_HLO + 2u * H_STAGE) // 81920

// ---------------------------------------------------------------------------
// W2 transpose + bf16 split: g_WT[pred][n][k] = split(W2[k][n])
// ---------------------------------------------------------------------------
__global__ __launch_bounds__(256) void split_W2T(
    const float* __restrict__ W2a, const float* __restrict__ W2b,
    const float* __restrict__ W2c)
{
    int pred = blockIdx.z;
    const float* W2 = (pred == 0) ? W2a : (pred == 1) ? W2b : W2c;
    int n0 = blockIdx.x * 32, k0 = blockIdx.y * 32;
    __shared__ float t[32][33];
    int tid = threadIdx.x;
    int c = tid & 31, r8 = tid >> 5;
    #pragma unroll
    for (int q = 0; q < 4; q++) {
        int k = r8 + q * 8;
        t[k][c] = W2[(size_t)(k0 + k) * D2 + n0 + c];
    }
    __syncthreads();
    #pragma unroll
    for (int q = 0; q < 4; q++) {
        int n = r8 + q * 8;
        float v = t[c][n];
        __nv_bfloat16 hi = __float2bfloat16(v);
        __nv_bfloat16 lo = __float2bfloat16(v - __bfloat162float(hi));
        size_t idx = (size_t)pred * D2 * D2 + (size_t)(n0 + n) * D2 + (k0 + c);
        g_WT_hi[idx] = hi;
        g_WT_lo[idx] = lo;
    }
}

// ---------------------------------------------------------------------------
// Precompute A and C for p1..p3 (GEMM1 factorization). grid (128,3), block 256.
// ---------------------------------------------------------------------------
__global__ __launch_bounds__(256) void precompute_AC(
    const float* __restrict__ emb,
    const float* __restrict__ W1a, const float* __restrict__ b1a,
    const float* __restrict__ W1b, const float* __restrict__ b1b,
    const float* __restrict__ W1c, const float* __restrict__ b1c)
{
    int pred = blockIdx.y;
    const float* W1 = (pred == 0) ? W1a : (pred == 1) ? W1b : W1c;
    const float* b1 = (pred == 0) ? b1a : (pred == 1) ? b1b : b1c;
    int row0 = blockIdx.x * 16;

    __shared__ float Xs[16][FDIM];
    int tid = threadIdx.x;
    #pragma unroll
    for (int q = 0; q < 8; q++) {
        int e = tid + 256 * q;
        Xs[e >> 7][e & 127] = emb[(size_t)row0 * FDIM + e];
    }
    __syncthreads();

    int c = tid;
    float accA[16], accC[16];
    float bb = b1[c];
    #pragma unroll
    for (int r = 0; r < 16; r++) { accA[r] = bb; accC[r] = 0.0f; }

    for (int k = 0; k < FDIM; k++) {
        float wA = W1[(size_t)k * D2 + c];
        float wC = W1[(size_t)(FDIM + k) * D2 + c];
        #pragma unroll
        for (int r = 0; r < 16; r++) {
            float x = Xs[r][k];
            accA[r] = fmaf(x, wA, accA[r]);
            accC[r] = fmaf(x, wC, accC[r]);
        }
    }
    float* Ap = g_A + ((size_t)pred * ROWS1 + row0) * D2 + c;
    float* Cp = g_C + ((size_t)pred * ROWS1 + row0) * D2 + c;
    #pragma unroll
    for (int r = 0; r < 16; r++) {
        Ap[(size_t)r * D2] = accA[r];
        Cp[(size_t)r * D2] = accC[r];
    }
}

// ---------------------------------------------------------------------------
// p0: fused residual MLP on 2048x128 rows. grid 128, blk 128.
// ---------------------------------------------------------------------------
__global__ __launch_bounds__(128) void p0_kernel(
    const float* __restrict__ emb,
    const float* __restrict__ W1, const float* __restrict__ b1,
    const float* __restrict__ W2, const float* __restrict__ b2,
    float* __restrict__ out)
{
    int row0 = blockIdx.x * 16;
    __shared__ float Xs[16][FDIM];
    __shared__ float Hs[16][FDIM];
    int tid = threadIdx.x;
    #pragma unroll
    for (int q = 0; q < 16; q++) {
        int e = tid + 128 * q;
        Xs[e >> 7][e & 127] = emb[(size_t)row0 * FDIM + e];
    }
    __syncthreads();

    int c = tid;
    float acc[16];
    float bb = b1[c];
    #pragma unroll
    for (int r = 0; r < 16; r++) acc[r] = bb;
    for (int k = 0; k < FDIM; k++) {
        float w = W1[(size_t)k * FDIM + c];
        #pragma unroll
        for (int r = 0; r < 16; r++) acc[r] = fmaf(Xs[r][k], w, acc[r]);
    }
    #pragma unroll
    for (int r = 0; r < 16; r++) Hs[r][c] = mish_fast(acc[r]);
    __syncthreads();

    float bb2 = b2[c];
    #pragma unroll
    for (int r = 0; r < 16; r++) acc[r] = bb2;
    for (int k = 0; k < FDIM; k++) {
        float w = W2[(size_t)k * FDIM + c];
        #pragma unroll
        for (int r = 0; r < 16; r++) acc[r] = fmaf(Hs[r][k], w, acc[r]);
    }
    #pragma unroll
    for (int r = 0; r < 16; r++)
        out[(size_t)(row0 + r) * FDIM + c] = Xs[r][c] + acc[r];
}

// ---------------------------------------------------------------------------
// Pair kernel via mma.sync bf16 (3-term split). One CTA per
// (pred, n-half, b, i-pair): M=128 (2 i x 64 j) x N=128 (one half of 256).
// 256 threads / 8 warps (warp tile m32 x n64), __launch_bounds__(256,2)
// -> 2 CTAs/SM so load/mish/epilogue of one CTA overlaps mma of the other.
// ---------------------------------------------------------------------------
__global__ __launch_bounds__(256, 2) void pair_mma_kernel(
    const float* __restrict__ emb,
    const float* __restrict__ b2a, const float* __restrict__ b2b,
    const float* __restrict__ b2c,
    float* __restrict__ out1)
{
    extern __shared__ char sptr[];
    uint32_t sbase = smem_u32(sptr);

    int tid = threadIdx.x;
    int wid = tid >> 5;
    int lane = tid & 31;
    int warpM = wid & 3;       // 4 groups of 32 M-rows
    int warpN = wid >> 2;      // 2 groups of 64 N-cols
    int i0 = blockIdx.x * 2, b = blockIdx.y;
    int pred = blockIdx.z >> 1;
    int nhalf = blockIdx.z & 1;
    int n0 = nhalf * 128;
    const float* b2 = (pred == 0) ? b2a : (pred == 1) ? b2b : b2c;

    const float* Arow0 = g_A + ((size_t)pred * ROWS1 + b * NOBJ + i0) * D2;
    const float* Cbase = g_C + ((size_t)pred * ROWS1 + b * NOBJ) * D2;
    const __nv_bfloat16* WHi = g_WT_hi + (size_t)pred * D2 * D2 + (size_t)n0 * D2;
    const __nv_bfloat16* WLo = g_WT_lo + (size_t)pred * D2 * D2 + (size_t)n0 * D2;

    float acc[2][8][4];
    #pragma unroll
    for (int mt = 0; mt < 2; mt++)
        #pragma unroll
        for (int nt = 0; nt < 8; nt++)
            #pragma unroll
            for (int q = 0; q < 4; q++) acc[mt][nt][q] = 0.0f;

    // ---- W chunk loader (cp.async): 128n x 32k, hi+lo -> stage st ----
    auto loadW = [&](int kc, int st) {
        #pragma unroll
        for (int q = 0; q < 4; q++) {
            int idx = tid + 256 * q;          // 0..1023 16B-granules
            int split = idx >> 9;
            int r = idx & 511;
            int n = r >> 2, gi = r & 3;
            const __nv_bfloat16* src =
                (split ? WLo : WHi) + (size_t)n * D2 + kc + gi * 8;
            uint32_t dst = sbase + (split ? OFF_WLO : OFF_WHI)
                         + (uint32_t)st * W_STAGE + n * ROWB + gi * 16;
            cp16(dst, src);
        }
    };

    // ---- H chunk: 128m x 32k mish + bf16 split -> stage st ----
    auto computeH = [&](int kc, int st) {
        int m = tid >> 1, ko = (tid & 1) * 16;
        const float* aP = Arow0 + (m >> 6) * D2 + kc + ko;
        const float* cP = Cbase + (size_t)(m & 63) * D2 + kc + ko;
        float h[16];
        #pragma unroll
        for (int q = 0; q < 4; q++) {
            float4 a = *(const float4*)(aP + 4 * q);
            float4 c = *(const float4*)(cP + 4 * q);
            h[4*q+0] = mish_fast(a.x + c.x);
            h[4*q+1] = mish_fast(a.y + c.y);
            h[4*q+2] = mish_fast(a.z + c.z);
            h[4*q+3] = mish_fast(a.w + c.w);
        }
        uint32_t hw[8], lw[8];
        #pragma unroll
        for (int q = 0; q < 8; q++) {
            __nv_bfloat16 h0 = __float2bfloat16(h[2*q]);
            __nv_bfloat16 h1 = __float2bfloat16(h[2*q+1]);
            __nv_bfloat162 hp; hp.x = h0; hp.y = h1;
            __nv_bfloat162 lp;
            lp.x = __float2bfloat16(h[2*q]   - __bfloat162float(h0));
            lp.y = __float2bfloat16(h[2*q+1] - __bfloat162float(h1));
            hw[q] = *reinterpret_cast<uint32_t*>(&hp);
            lw[q] = *reinterpret_cast<uint32_t*>(&lp);
        }
        uint32_t off = (uint32_t)st * H_STAGE + m * ROWB + ko * 2;
        *(uint4*)(sptr + OFF_HHI + off)      = make_uint4(hw[0], hw[1], hw[2], hw[3]);
        *(uint4*)(sptr + OFF_HHI + off + 16) = make_uint4(hw[4], hw[5], hw[6], hw[7]);
        *(uint4*)(sptr + OFF_HLO + off)      = make_uint4(lw[0], lw[1], lw[2], lw[3]);
        *(uint4*)(sptr + OFF_HLO + off + 16) = make_uint4(lw[4], lw[5], lw[6], lw[7]);
    };

    // ---- MMA over one k-chunk (32) in stage st ----
    auto mmaChunk = [&](int st) {
        uint32_t hHi = sbase + OFF_HHI + (uint32_t)st * H_STAGE;
        uint32_t hLo = sbase + OFF_HLO + (uint32_t)st * H_STAGE;
        uint32_t wHi = sbase + OFF_WHI + (uint32_t)st * W_STAGE;
        uint32_t wLo = sbase + OFF_WLO + (uint32_t)st * W_STAGE;
        #pragma unroll
        for (int ks = 0; ks < 2; ks++) {
            int kl = ks * 16;
            uint32_t ahi[2][4], alo[2][4];
            int arow = lane & 15;
            int acol = kl + ((lane >> 4) << 3);
            #pragma unroll
            for (int mt = 0; mt < 2; mt++) {
                uint32_t rowG = warpM * 32 + mt * 16 + arow;
                ldsm4(ahi[mt], hHi + rowG * ROWB + acol * 2);
                ldsm4(alo[mt], hLo + rowG * ROWB + acol * 2);
            }
            int g = lane >> 3;
            int brow = (g >> 1) * 8 + (lane & 7);
            int bcol = kl + ((g & 1) << 3);
            #pragma unroll
            for (int p = 0; p < 4; p++) {
                uint32_t nG = warpN * 64 + p * 16 + brow;
                uint32_t bhi[4], blo[4];
                ldsm4(bhi, wHi + nG * ROWB + bcol * 2);
                ldsm4(blo, wLo + nG * ROWB + bcol * 2);
                #pragma unroll
                for (int mt = 0; mt < 2; mt++) {
                    #pragma unroll
                    for (int hh = 0; hh < 2; hh++) {
                        float* d = acc[mt][p * 2 + hh];
                        mma16816(d, ahi[mt], &bhi[hh * 2]);
                        mma16816(d, ahi[mt], &blo[hh * 2]);
                        mma16816(d, alo[mt], &bhi[hh * 2]);
                    }
                }
            }
        }
    };

    // ---- pipelined main loop ----
    loadW(0, 0); CP_COMMIT();
    computeH(0, 0);
    CP_WAIT0();
    __syncthreads();
    #pragma unroll 1
    for (int c = 0; c < 8; c++) {
        int cur = c & 1, nxt = cur ^ 1;
        if (c < 7) {
            loadW((c + 1) * KCH, nxt); CP_COMMIT();
            computeH((c + 1) * KCH, nxt);
        }
        mmaChunk(cur);
        if (c < 7) CP_WAIT0();
        __syncthreads();
    }

    // ---- epilogue: residual + bias, st.v2 ----
    int rowTile = lane >> 2, colq = (lane & 3) * 2;
    #pragma unroll
    for (int mt = 0; mt < 2; mt++) {
        #pragma unroll
        for (int rh = 0; rh < 2; rh++) {
            int mG = warpM * 32 + mt * 16 + rh * 8 + rowTile;
            int ii = mG >> 6, j = mG & 63;
            // cols [0,128): residual = x_i[col]; cols [128,256): x_j[col-128]
            const float* resP = (nhalf == 0)
                ? emb + (size_t)(b * NOBJ + i0 + ii) * FDIM
                : emb + (size_t)(b * NOBJ + j) * FDIM;
            float* orow = out1 + (size_t)pred * PAIR_SIZE
                        + (size_t)((b * NOBJ + i0 + ii) * NOBJ + j) * D2;
            #pragma unroll
            for (int nt = 0; nt < 8; nt++) {
                int col = n0 + warpN * 64 + nt * 8 + colq;
                float2 res  = *(const float2*)(resP + (col & 127));
                float2 bias = *(const float2*)(b2 + col);
                float2 v;
                v.x = acc[mt][nt][rh * 2 + 0] + res.x + bias.x;
                v.y = acc[mt][nt][rh * 2 + 1] + res.y + bias.y;
                *(float2*)(orow + col) = v;
            }
        }
    }
}

// ---------------------------------------------------------------------------
extern "C" void kernel_launch(void* const* d_in, const int* in_sizes, int n_in,
                              void* d_out, int out_size)
{
    const float* emb   = (const float*)d_in[0];
    const float* W1_p0 = (const float*)d_in[2];
    const float* b1_p0 = (const float*)d_in[3];
    const float* W2_p0 = (const float*)d_in[4];
    const float* b2_p0 = (const float*)d_in[5];
    const float* W1_p1 = (const float*)d_in[6];
    const float* b1_p1 = (const float*)d_in[7];
    const float* W2_p1 = (const float*)d_in[8];
    const float* b2_p1 = (const float*)d_in[9];
    const float* W1_p2 = (const float*)d_in[10];
    const float* b1_p2 = (const float*)d_in[11];
    const float* W2_p2 = (const float*)d_in[12];
    const float* b2_p2 = (const float*)d_in[13];
    const float* W1_p3 = (const float*)d_in[14];
    const float* b1_p3 = (const float*)d_in[15];
    const float* W2_p3 = (const float*)d_in[16];
    const float* b2_p3 = (const float*)d_in[17];

    float* out = (float*)d_out;

    cudaFuncSetAttribute(pair_mma_kernel,
                         cudaFuncAttributeMaxDynamicSharedMemorySize, SMEM_PAIR);

    split_W2T<<<dim3(8, 8, 3), 256>>>(W2_p1, W2_p2, W2_p3);

    precompute_AC<<<dim3(ROWS1 / 16, 3), 256>>>(
        emb, W1_p1, b1_p1, W1_p2, b1_p2, W1_p3, b1_p3);

    p0_kernel<<<ROWS1 / 16, 128>>>(emb, W1_p0, b1_p0, W2_p0, b2_p0, out);

    pair_mma_kernel<<<dim3(NOBJ / 2, BATCH, 6), 256, SMEM_PAIR>>>(
        emb, b2_p1, b2_p2, b2_p3, out + P0_SIZE);
}